// round 7
// baseline (speedup 1.0000x reference)
#include <cuda_runtime.h>
#include <cuda_bf16.h>
#include <cuda_fp16.h>
#include <cstdint>

#define NB 8
#define HW 4096
#define CI 256
#define CA 128
#define CO 256
#define INVS 0.08838834764831843f
#define PSC  0.015625f     // 2^-6 P scaling (fp16 headroom)
#define PSCI 64.0f

// flash SMEM layout (byte offsets, 16B-aligned)
#define QJ_STR   272       // 128 bf16 = 256B data + pad
#define FEAT_STR 144       // 64 fp16 = 128B data + pad
#define P_STR    144
#define QJ_BUF   17408     // 64*272
#define FEAT_BUF 36864     // 256*144
#define QJH_OFF  0
#define QJL_OFF  34816
#define FEAT_OFF 69632
#define P_OFF    143360    // 64*144 = 9216
#define MJ_OFF   152576    // 2*256
#define LRED_OFF 153088    // 256
#define SMEM_TOTAL 153600

__device__ __nv_bfloat16 g_qhi[NB * HW * CA];
__device__ __nv_bfloat16 g_qlo[NB * HW * CA];
__device__ __half g_featT[(size_t)NB * CO * HW];
__device__ float g_scale[CO + CA];
__device__ float g_bias[CO + CA];

__device__ __forceinline__ uint32_t smem_u32(const void* p) {
    uint32_t a;
    asm("{ .reg .u64 t; cvta.to.shared.u64 t, %1; cvt.u32.u64 %0, t; }" : "=r"(a) : "l"(p));
    return a;
}
#define CP16(dst, src) asm volatile("cp.async.cg.shared.global [%0], [%1], 16;" :: "r"(dst), "l"(src))
#define CP_COMMIT()    asm volatile("cp.async.commit_group;" ::: "memory")
#define CP_WAIT1()     asm volatile("cp.async.wait_group 1;" ::: "memory")
#define CP_WAIT0()     asm volatile("cp.async.wait_group 0;" ::: "memory")

#define LDSM_X4(r0, r1, r2, r3, addr) \
    asm volatile("ldmatrix.sync.aligned.m8n8.x4.shared.b16 {%0,%1,%2,%3}, [%4];" \
        : "=r"(r0), "=r"(r1), "=r"(r2), "=r"(r3) : "r"(addr))

__device__ __forceinline__ void mma_bf16(float* d, const uint32_t* a, const uint32_t* b) {
    asm volatile("mma.sync.aligned.m16n8k16.row.col.f32.bf16.bf16.f32 "
        "{%0,%1,%2,%3}, {%4,%5,%6,%7}, {%8,%9}, {%0,%1,%2,%3};"
        : "+f"(d[0]), "+f"(d[1]), "+f"(d[2]), "+f"(d[3])
        : "r"(a[0]), "r"(a[1]), "r"(a[2]), "r"(a[3]), "r"(b[0]), "r"(b[1]));
}
__device__ __forceinline__ void mma_f16(float* d, const uint32_t* a, const uint32_t* b) {
    asm volatile("mma.sync.aligned.m16n8k16.row.col.f32.f16.f16.f32 "
        "{%0,%1,%2,%3}, {%4,%5,%6,%7}, {%8,%9}, {%0,%1,%2,%3};"
        : "+f"(d[0]), "+f"(d[1]), "+f"(d[2]), "+f"(d[3])
        : "r"(a[0]), "r"(a[1]), "r"(a[2]), "r"(a[3]), "r"(b[0]), "r"(b[1]));
}

__global__ void prep_kernel(const float* __restrict__ rg, const float* __restrict__ rb,
                            const float* __restrict__ rm, const float* __restrict__ rv,
                            const float* __restrict__ ag, const float* __restrict__ ab,
                            const float* __restrict__ am, const float* __restrict__ av) {
    int o = threadIdx.x;
    if (o < CO) {
        float inv = rg[o] * rsqrtf(rv[o] + 1e-5f);
        g_scale[o] = inv; g_bias[o] = rb[o] - rm[o] * inv;
    } else if (o < CO + CA) {
        int a = o - CO;
        float inv = ag[a] * rsqrtf(av[a] + 1e-5f);
        g_scale[o] = inv; g_bias[o] = ab[a] - am[a] * inv;
    }
}

// conv1x1 + BN + ReLU -> fp16 featT[n][c][pos] and hi/lo-split bf16 q[n][pos][k]
__global__ __launch_bounds__(256) void proj_kernel(const float* __restrict__ x,
                                                   const float* __restrict__ reduc_w,
                                                   const float* __restrict__ att_w) {
    __shared__ float Ws[16][65];
    __shared__ float Xs[16][65];
    __shared__ float tbuf[64][65];
    const int pb = blockIdx.x * 64, ob = blockIdx.y * 64, n = blockIdx.z;
    const int t = threadIdx.x, tx = t & 15, ty = t >> 4;
    const int o0 = ty * 4, p0 = tx * 4;
    const float* W = (ob < CO) ? (reduc_w + ob * CI) : (att_w + (ob - CO) * CI);
    const float* X = x + (size_t)(n * CI) * HW + pb;

    float acc[4][4];
#pragma unroll
    for (int i = 0; i < 4; i++)
#pragma unroll
        for (int j = 0; j < 4; j++) acc[i][j] = 0.f;

    for (int kb = 0; kb < CI; kb += 16) {
        {
            int o = t >> 2, k0 = (t & 3) * 4;
            float4 w4 = *(const float4*)(W + o * CI + kb + k0);
            Ws[k0][o] = w4.x; Ws[k0+1][o] = w4.y; Ws[k0+2][o] = w4.z; Ws[k0+3][o] = w4.w;
        }
        {
            int p = t & 63, kk = t >> 6;
#pragma unroll
            for (int r = 0; r < 4; r++)
                Xs[kk + 4*r][p] = X[(size_t)(kb + kk + 4*r) * HW + p];
        }
        __syncthreads();
#pragma unroll
        for (int k = 0; k < 16; k++) {
            float a[4], b[4];
#pragma unroll
            for (int i = 0; i < 4; i++) a[i] = Ws[k][o0 + i];
#pragma unroll
            for (int j = 0; j < 4; j++) b[j] = Xs[k][p0 + j];
#pragma unroll
            for (int i = 0; i < 4; i++)
#pragma unroll
                for (int j = 0; j < 4; j++)
                    acc[i][j] = fmaf(a[i], b[j], acc[i][j]);
        }
        __syncthreads();
    }

    if (ob < CO) {
#pragma unroll
        for (int i = 0; i < 4; i++) {
            int o = ob + o0 + i;
            float sc = g_scale[o], bs = g_bias[o];
            float v0 = fmaxf(fmaf(acc[i][0], sc, bs), 0.f);
            float v1 = fmaxf(fmaf(acc[i][1], sc, bs), 0.f);
            float v2 = fmaxf(fmaf(acc[i][2], sc, bs), 0.f);
            float v3 = fmaxf(fmaf(acc[i][3], sc, bs), 0.f);
            __half2 h0 = __floats2half2_rn(v0, v1);
            __half2 h1 = __floats2half2_rn(v2, v3);
            uint2 pk = make_uint2(*(uint32_t*)&h0, *(uint32_t*)&h1);
            *(uint2*)(g_featT + ((size_t)n * CO + o) * HW + pb + p0) = pk;
        }
    } else {
#pragma unroll
        for (int i = 0; i < 4; i++) {
            float sc = g_scale[ob + o0 + i], bs = g_bias[ob + o0 + i];
#pragma unroll
            for (int j = 0; j < 4; j++)
                tbuf[o0 + i][p0 + j] = fmaxf(fmaf(acc[i][j], sc, bs), 0.f);
        }
        __syncthreads();
        if (t < 128) {
            int p = t & 63, half = t >> 6;
            __nv_bfloat16* dst = (half ? g_qlo : g_qhi) +
                                 ((size_t)(n * HW + pb + p)) * CA + (ob - CO);
#pragma unroll
            for (int k0 = 0; k0 < 64; k0 += 8) {
                uint32_t pk[4];
#pragma unroll
                for (int q = 0; q < 4; q++) {
                    float va = tbuf[k0 + 2*q][p], vb = tbuf[k0 + 2*q + 1][p];
                    __nv_bfloat16 ha = __float2bfloat16(va), hb = __float2bfloat16(vb);
                    __nv_bfloat162 bb;
                    if (half) bb = __floats2bfloat162_rn(va - __bfloat162float(ha),
                                                         vb - __bfloat162float(hb));
                    else { bb.x = ha; bb.y = hb; }
                    pk[q] = *(uint32_t*)&bb;
                }
                *(uint4*)(dst + k0) = make_uint4(pk[0], pk[1], pk[2], pk[3]);
            }
        }
    }
}

// flash attention on HMMA (mma.sync m16n8k16) + ldmatrix operand loads
__global__ __launch_bounds__(256, 1) void flash_kernel(const float* __restrict__ mask,
                                                       float* __restrict__ out) {
    extern __shared__ __align__(16) char sm[];
    const uint32_t smb = smem_u32(sm);
    const int n = blockIdx.y, ib = blockIdx.x * 64;
    const int tid = threadIdx.x, w = tid >> 5, lane = tid & 31;
    const int gid = lane >> 2, tig = lane & 3;
    const int g = w >> 1, jh = w & 1;
    const int lq = lane >> 3, lr = lane & 7;   // ldmatrix: matrix idx, row-in-matrix

    // hoisted ldmatrix per-thread byte offsets
    // QK B (rows=[n][k] bf16): u selects jq pair; m0/m1 = n0-7 k0/k8, m2/m3 = n8-15 k0/k8
    uint32_t qkb_off[2];
#pragma unroll
    for (int u = 0; u < 2; u++)
        qkb_off[u] = (uint32_t)((jh * 32 + u * 16 + ((lq & 2) ? 8 : 0) + lr) * QJ_STR +
                                ((lq & 1) ? 16 : 0));
    // PV A (feat rows=[c][pos] fp16): m0/m1 = c0-7/c8-15 k0, m2/m3 = k8
    const uint32_t pva_off = (uint32_t)((jh * 128 + ((lq & 1) ? 8 : 0) + lr) * FEAT_STR +
                                        ((lq & 2) ? 16 : 0));
    // PV B (P rows=[i][j] fp16): m0/m1 = i0-7 k0/k8, m2/m3 = i8-15 k0/k8
    const uint32_t pvb_off = (uint32_t)((g * 16 + ((lq & 2) ? 8 : 0) + lr) * P_STR +
                                        ((lq & 1) ? 16 : 0));

    // Qi A-fragments (hi/lo) in registers for the whole j loop
    uint32_t ah[8][4], al[8][4];
    {
        const size_t r0 = (size_t)(n * HW + ib + g * 16 + gid) * CA;
        const size_t r1 = r0 + 8 * CA;
#pragma unroll
        for (int ks = 0; ks < 8; ks++) {
            int c0 = ks * 16 + 2 * tig;
            ah[ks][0] = *(const uint32_t*)(g_qhi + r0 + c0);
            ah[ks][1] = *(const uint32_t*)(g_qhi + r1 + c0);
            ah[ks][2] = *(const uint32_t*)(g_qhi + r0 + c0 + 8);
            ah[ks][3] = *(const uint32_t*)(g_qhi + r1 + c0 + 8);
            al[ks][0] = *(const uint32_t*)(g_qlo + r0 + c0);
            al[ks][1] = *(const uint32_t*)(g_qlo + r1 + c0);
            al[ks][2] = *(const uint32_t*)(g_qlo + r0 + c0 + 8);
            al[ks][3] = *(const uint32_t*)(g_qlo + r1 + c0 + 8);
        }
    }

    auto prefetch = [&](int t) {
        const int buf = t & 1, jb = t * 64;
        const uint32_t qh = smb + QJH_OFF + buf * QJ_BUF;
        const uint32_t ql = smb + QJL_OFF + buf * QJ_BUF;
#pragma unroll
        for (int it = 0; it < 4; it++) {
            int e = tid + it * 256, row = e >> 4, ch = e & 15;
            size_t go = (size_t)(n * HW + jb + row) * CA + ch * 8;
            CP16(qh + row * QJ_STR + ch * 16, (const char*)(g_qhi + go));
            CP16(ql + row * QJ_STR + ch * 16, (const char*)(g_qlo + go));
        }
        const uint32_t fb = smb + FEAT_OFF + buf * FEAT_BUF;
#pragma unroll
        for (int it = 0; it < 8; it++) {
            int e = tid + it * 256, row = e >> 3, ch = e & 7;
            CP16(fb + row * FEAT_STR + ch * 16,
                 (const char*)(g_featT + ((size_t)n * CO + row) * HW + jb + ch * 8));
        }
        if (tid < 16)
            CP16(smb + MJ_OFF + buf * 256 + tid * 16, (const char*)(mask + n * HW + jb + tid * 4));
        CP_COMMIT();
    };

    float dacc[8][2][4];
#pragma unroll
    for (int mt = 0; mt < 8; mt++)
#pragma unroll
        for (int nb = 0; nb < 2; nb++)
#pragma unroll
            for (int r = 0; r < 4; r++) dacc[mt][nb][r] = 0.f;
    float l0 = 0.f, l1 = 0.f;

    prefetch(0);

    for (int t = 0; t < 64; t++) {
        __syncthreads();                    // prior PV reads of buf (t+1)&1 done
        if (t < 63) { prefetch(t + 1); CP_WAIT1(); } else { CP_WAIT0(); }
        __syncthreads();                    // buf t visible CTA-wide
        const int buf = t & 1;

        // ---- QK: S[16i x 32j] via 3 bf16 passes (hh, hl, lh), ldmatrix B ----
        float s[4][4];
#pragma unroll
        for (int jq = 0; jq < 4; jq++)
#pragma unroll
            for (int r = 0; r < 4; r++) s[jq][r] = 0.f;
#pragma unroll
        for (int pass = 0; pass < 3; pass++) {
            const uint32_t qbase = smb + ((pass == 1) ? QJL_OFF : QJH_OFF) + buf * QJ_BUF;
#pragma unroll
            for (int ks = 0; ks < 8; ks++) {
                const uint32_t* a = (pass == 2) ? al[ks] : ah[ks];
#pragma unroll
                for (int u = 0; u < 2; u++) {
                    uint32_t r0, r1, r2, r3;
                    LDSM_X4(r0, r1, r2, r3, qbase + qkb_off[u] + ks * 32);
                    uint32_t b0[2] = {r0, r1}, b1[2] = {r2, r3};
                    mma_bf16(s[u * 2],     a, b0);
                    mma_bf16(s[u * 2 + 1], a, b1);
                }
            }
        }

        // ---- softmax (no-max; scores bounded) -> scaled fp16 P in SMEM ----
        const float* mjb = (const float*)(sm + MJ_OFF + buf * 256);
        char* P = sm + P_OFF;
#pragma unroll
        for (int jq = 0; jq < 4; jq++) {
            int j8 = jh * 32 + jq * 8;
            float m0 = (mjb[j8 + 2 * tig]     - 1.f) * 1e8f;
            float m1 = (mjb[j8 + 2 * tig + 1] - 1.f) * 1e8f;
            float p0 = __expf(fmaf(s[jq][0], INVS, m0));
            float p1 = __expf(fmaf(s[jq][1], INVS, m1));
            float p2 = __expf(fmaf(s[jq][2], INVS, m0));
            float p3 = __expf(fmaf(s[jq][3], INVS, m1));
            l0 += p0 + p1; l1 += p2 + p3;
            __half2 q01 = __floats2half2_rn(p0 * PSC, p1 * PSC);
            __half2 q23 = __floats2half2_rn(p2 * PSC, p3 * PSC);
            *(uint32_t*)(P + (g * 16 + gid)     * P_STR + (j8 + 2 * tig) * 2) = *(uint32_t*)&q01;
            *(uint32_t*)(P + (g * 16 + 8 + gid) * P_STR + (j8 + 2 * tig) * 2) = *(uint32_t*)&q23;
        }
        // P rows of group g touched only by warps (g,0),(g,1): pair-local barrier
        asm volatile("bar.sync %0, 64;" :: "r"(1 + g) : "memory");

        // ---- PV: dacc[c16 x i16] += feat @ P^T, ldmatrix A and B ----
        uint32_t bp[4][2][2];
        const uint32_t Pb = smb + P_OFF;
#pragma unroll
        for (int ks = 0; ks < 4; ks++)
            LDSM_X4(bp[ks][0][0], bp[ks][0][1], bp[ks][1][0], bp[ks][1][1],
                    Pb + pvb_off + ks * 32);
        const uint32_t fbb = smb + FEAT_OFF + buf * FEAT_BUF;
#pragma unroll
        for (int ks = 0; ks < 4; ks++) {
#pragma unroll
            for (int mt = 0; mt < 8; mt++) {
                uint32_t a0, a1, a2, a3;
                LDSM_X4(a0, a1, a2, a3, fbb + pva_off + mt * (16 * FEAT_STR) + ks * 32);
                uint32_t aa[4] = {a0, a1, a2, a3};
                mma_f16(dacc[mt][0], aa, bp[ks][0]);
                mma_f16(dacc[mt][1], aa, bp[ks][1]);
            }
        }
    }

    // ---- l reduction (quad shuffle + cross-warp-pair via SMEM) ----
    l0 += __shfl_xor_sync(0xFFFFFFFFu, l0, 1);
    l0 += __shfl_xor_sync(0xFFFFFFFFu, l0, 2);
    l1 += __shfl_xor_sync(0xFFFFFFFFu, l1, 1);
    l1 += __shfl_xor_sync(0xFFFFFFFFu, l1, 2);
    float* lred = (float*)(sm + LRED_OFF);
    __syncthreads();
    if (jh == 0 && tig == 0) { lred[g * 16 + gid] = l0; lred[g * 16 + 8 + gid] = l1; }
    __syncthreads();
    if (jh == 1 && tig == 0) { lred[g * 16 + gid] += l0; lred[g * 16 + 8 + gid] += l1; }
    __syncthreads();

    // ---- epilogue: out[c][i] = dacc * 64 / l * mask_i ----
#pragma unroll
    for (int nb = 0; nb < 2; nb++) {
        int i0 = g * 16 + nb * 8 + 2 * tig;
        float r0 = mask[n * HW + ib + i0]     * PSCI / fmaxf(lred[i0],     1e-30f);
        float r1 = mask[n * HW + ib + i0 + 1] * PSCI / fmaxf(lred[i0 + 1], 1e-30f);
#pragma unroll
        for (int mt = 0; mt < 8; mt++) {
            int c = jh * 128 + mt * 16 + gid;
            float2 v0 = make_float2(dacc[mt][nb][0] * r0, dacc[mt][nb][1] * r1);
            float2 v1 = make_float2(dacc[mt][nb][2] * r0, dacc[mt][nb][3] * r1);
            *(float2*)(out + ((size_t)(n * CO + c))     * HW + ib + i0) = v0;
            *(float2*)(out + ((size_t)(n * CO + c + 8)) * HW + ib + i0) = v1;
        }
    }
}

extern "C" void kernel_launch(void* const* d_in, const int* in_sizes, int n_in,
                              void* d_out, int out_size) {
    const float* x    = (const float*)d_in[0];
    const float* mask = (const float*)d_in[1];
    prep_kernel<<<1, CO + CA>>>((const float*)d_in[3], (const float*)d_in[4],
                                (const float*)d_in[5], (const float*)d_in[6],
                                (const float*)d_in[8], (const float*)d_in[9],
                                (const float*)d_in[10], (const float*)d_in[11]);
    dim3 gproj(HW / 64, (CO + CA) / 64, NB);
    proj_kernel<<<gproj, 256>>>(x, (const float*)d_in[2], (const float*)d_in[7]);

    cudaFuncSetAttribute(flash_kernel, cudaFuncAttributeMaxDynamicSharedMemorySize, SMEM_TOTAL);
    dim3 gfl(HW / 64, NB);
    flash_kernel<<<gfl, 256, SMEM_TOTAL>>>(mask, (float*)d_out);
}

// round 8
// speedup vs baseline: 1.5509x; 1.5509x over previous
#include <cuda_runtime.h>
#include <cuda_bf16.h>
#include <cuda_fp16.h>
#include <cstdint>

#define NB 8
#define HW 4096
#define CI 256
#define CA 128
#define CO 256
#define INVS 0.08838834764831843f
#define PSC  0.015625f     // 2^-6 P scaling (fp16 headroom)
#define PSCI 64.0f

// flash SMEM layout (byte offsets; XOR-swizzled rows, no padding)
#define QJ_OFF   0         // 2 x 16384 (64 rows x 256B)
#define QJ_BUF   16384
#define FEAT_OFF 32768     // 2 x 32768 (256 rows x 128B)
#define FEAT_BUF 32768
#define P_OFF    98304     // 64 rows x 128B = 8192
#define MJ_OFF   106496    // 2 x 256
#define LRED_OFF 107008    // 256
#define SMEM_TOTAL 107520

__device__ __half g_q[NB * HW * CA];                 // fp16 q [n][pos][128]
__device__ __half g_featT[(size_t)NB * CO * HW];     // fp16 feat [n][c][pos]
__device__ float g_scale[CO + CA];
__device__ float g_bias[CO + CA];

__device__ __forceinline__ uint32_t smem_u32(const void* p) {
    uint32_t a;
    asm("{ .reg .u64 t; cvta.to.shared.u64 t, %1; cvt.u32.u64 %0, t; }" : "=r"(a) : "l"(p));
    return a;
}
#define CP16(dst, src) asm volatile("cp.async.cg.shared.global [%0], [%1], 16;" :: "r"(dst), "l"(src))
#define CP_COMMIT()    asm volatile("cp.async.commit_group;" ::: "memory")
#define CP_WAIT1()     asm volatile("cp.async.wait_group 1;" ::: "memory")
#define CP_WAIT0()     asm volatile("cp.async.wait_group 0;" ::: "memory")

#define LDSM_X4(r0, r1, r2, r3, addr) \
    asm volatile("ldmatrix.sync.aligned.m8n8.x4.shared.b16 {%0,%1,%2,%3}, [%4];" \
        : "=r"(r0), "=r"(r1), "=r"(r2), "=r"(r3) : "r"(addr))

__device__ __forceinline__ void mma_f16(float* d, const uint32_t* a, const uint32_t* b) {
    asm volatile("mma.sync.aligned.m16n8k16.row.col.f32.f16.f16.f32 "
        "{%0,%1,%2,%3}, {%4,%5,%6,%7}, {%8,%9}, {%0,%1,%2,%3};"
        : "+f"(d[0]), "+f"(d[1]), "+f"(d[2]), "+f"(d[3])
        : "r"(a[0]), "r"(a[1]), "r"(a[2]), "r"(a[3]), "r"(b[0]), "r"(b[1]));
}

__global__ void prep_kernel(const float* __restrict__ rg, const float* __restrict__ rb,
                            const float* __restrict__ rm, const float* __restrict__ rv,
                            const float* __restrict__ ag, const float* __restrict__ ab,
                            const float* __restrict__ am, const float* __restrict__ av) {
    int o = threadIdx.x;
    if (o < CO) {
        float inv = rg[o] * rsqrtf(rv[o] + 1e-5f);
        g_scale[o] = inv; g_bias[o] = rb[o] - rm[o] * inv;
    } else if (o < CO + CA) {
        int a = o - CO;
        float inv = ag[a] * rsqrtf(av[a] + 1e-5f);
        g_scale[o] = inv; g_bias[o] = ab[a] - am[a] * inv;
    }
}

// conv1x1 + BN + ReLU -> fp16 featT[n][c][pos] and fp16 q[n][pos][k]
__global__ __launch_bounds__(256) void proj_kernel(const float* __restrict__ x,
                                                   const float* __restrict__ reduc_w,
                                                   const float* __restrict__ att_w) {
    __shared__ float Ws[16][65];
    __shared__ float Xs[16][65];
    __shared__ float tbuf[64][65];
    const int pb = blockIdx.x * 64, ob = blockIdx.y * 64, n = blockIdx.z;
    const int t = threadIdx.x, tx = t & 15, ty = t >> 4;
    const int o0 = ty * 4, p0 = tx * 4;
    const float* W = (ob < CO) ? (reduc_w + ob * CI) : (att_w + (ob - CO) * CI);
    const float* X = x + (size_t)(n * CI) * HW + pb;

    float acc[4][4];
#pragma unroll
    for (int i = 0; i < 4; i++)
#pragma unroll
        for (int j = 0; j < 4; j++) acc[i][j] = 0.f;

    for (int kb = 0; kb < CI; kb += 16) {
        {
            int o = t >> 2, k0 = (t & 3) * 4;
            float4 w4 = *(const float4*)(W + o * CI + kb + k0);
            Ws[k0][o] = w4.x; Ws[k0+1][o] = w4.y; Ws[k0+2][o] = w4.z; Ws[k0+3][o] = w4.w;
        }
        {
            int p = t & 63, kk = t >> 6;
#pragma unroll
            for (int r = 0; r < 4; r++)
                Xs[kk + 4*r][p] = X[(size_t)(kb + kk + 4*r) * HW + p];
        }
        __syncthreads();
#pragma unroll
        for (int k = 0; k < 16; k++) {
            float a[4], b[4];
#pragma unroll
            for (int i = 0; i < 4; i++) a[i] = Ws[k][o0 + i];
#pragma unroll
            for (int j = 0; j < 4; j++) b[j] = Xs[k][p0 + j];
#pragma unroll
            for (int i = 0; i < 4; i++)
#pragma unroll
                for (int j = 0; j < 4; j++)
                    acc[i][j] = fmaf(a[i], b[j], acc[i][j]);
        }
        __syncthreads();
    }

    if (ob < CO) {
#pragma unroll
        for (int i = 0; i < 4; i++) {
            int o = ob + o0 + i;
            float sc = g_scale[o], bs = g_bias[o];
            float v0 = fmaxf(fmaf(acc[i][0], sc, bs), 0.f);
            float v1 = fmaxf(fmaf(acc[i][1], sc, bs), 0.f);
            float v2 = fmaxf(fmaf(acc[i][2], sc, bs), 0.f);
            float v3 = fmaxf(fmaf(acc[i][3], sc, bs), 0.f);
            __half2 h0 = __floats2half2_rn(v0, v1);
            __half2 h1 = __floats2half2_rn(v2, v3);
            uint2 pk = make_uint2(*(uint32_t*)&h0, *(uint32_t*)&h1);
            *(uint2*)(g_featT + ((size_t)n * CO + o) * HW + pb + p0) = pk;
        }
    } else {
#pragma unroll
        for (int i = 0; i < 4; i++) {
            float sc = g_scale[ob + o0 + i], bs = g_bias[ob + o0 + i];
#pragma unroll
            for (int j = 0; j < 4; j++)
                tbuf[o0 + i][p0 + j] = fmaxf(fmaf(acc[i][j], sc, bs), 0.f);
        }
        __syncthreads();
        if (t < 64) {
            int p = t;
            __half* dst = g_q + ((size_t)(n * HW + pb + p)) * CA + (ob - CO);
#pragma unroll
            for (int k0 = 0; k0 < 64; k0 += 8) {
                uint32_t pk[4];
#pragma unroll
                for (int q = 0; q < 4; q++) {
                    __half2 hh = __floats2half2_rn(tbuf[k0 + 2*q][p], tbuf[k0 + 2*q + 1][p]);
                    pk[q] = *(uint32_t*)&hh;
                }
                *(uint4*)(dst + k0) = make_uint4(pk[0], pk[1], pk[2], pk[3]);
            }
        }
    }
}

// flash attention: fp16 HMMA, XOR-swizzled SMEM, 2 CTAs/SM
__global__ __launch_bounds__(256, 2) void flash_kernel(const float* __restrict__ mask,
                                                       float* __restrict__ out) {
    extern __shared__ __align__(16) char sm[];
    const uint32_t smb = smem_u32(sm);
    const int n = blockIdx.y, ib = blockIdx.x * 64;
    const int tid = threadIdx.x, w = tid >> 5, lane = tid & 31;
    const int gid = lane >> 2, tig = lane & 3;
    const int g = w >> 1, jh = w & 1;
    const int lq = lane >> 3, lr = lane & 7;

    // hoisted ldmatrix row bases (all reader rows have row&7 == lr)
    uint32_t qjrow[2];
#pragma unroll
    for (int u = 0; u < 2; u++)
        qjrow[u] = (uint32_t)((jh * 32 + u * 16 + ((lq & 2) ? 8 : 0) + lr) * 256);
    const int qk_c0 = lq & 1;                       // QK B chunk lsb
    const uint32_t pvarow = (uint32_t)((jh * 128 + ((lq & 1) ? 8 : 0) + lr) * 128);
    const int pva_c0 = (lq & 2) >> 1;               // PV A chunk lsb
    const uint32_t pvbrow = smb + P_OFF + (uint32_t)((g * 16 + ((lq & 2) ? 8 : 0) + lr) * 128);
    const int pvb_c0 = lq & 1;

    // Qi A-fragments in registers for the whole j loop
    uint32_t ah[8][4];
    {
        const size_t r0 = (size_t)(n * HW + ib + g * 16 + gid) * CA;
        const size_t r1 = r0 + 8 * CA;
#pragma unroll
        for (int ks = 0; ks < 8; ks++) {
            int c0 = ks * 16 + 2 * tig;
            ah[ks][0] = *(const uint32_t*)(g_q + r0 + c0);
            ah[ks][1] = *(const uint32_t*)(g_q + r1 + c0);
            ah[ks][2] = *(const uint32_t*)(g_q + r0 + c0 + 8);
            ah[ks][3] = *(const uint32_t*)(g_q + r1 + c0 + 8);
        }
    }

    auto prefetch = [&](int t) {
        const int buf = t & 1, jb = t * 64;
        const uint32_t qh = smb + QJ_OFF + buf * QJ_BUF;
#pragma unroll
        for (int it = 0; it < 4; it++) {
            int e = tid + it * 256, row = e >> 4, ch = e & 15;
            CP16(qh + row * 256 + ((ch ^ (row & 7)) << 4),
                 (const char*)(g_q + (size_t)(n * HW + jb + row) * CA + ch * 8));
        }
        const uint32_t fb = smb + FEAT_OFF + buf * FEAT_BUF;
#pragma unroll
        for (int it = 0; it < 8; it++) {
            int e = tid + it * 256, row = e >> 3, ch = e & 7;
            CP16(fb + row * 128 + ((ch ^ (row & 7)) << 4),
                 (const char*)(g_featT + ((size_t)n * CO + row) * HW + jb + ch * 8));
        }
        if (tid < 16)
            CP16(smb + MJ_OFF + buf * 256 + tid * 16, (const char*)(mask + n * HW + jb + tid * 4));
        CP_COMMIT();
    };

    float dacc[8][2][4];
#pragma unroll
    for (int mt = 0; mt < 8; mt++)
#pragma unroll
        for (int nb = 0; nb < 2; nb++)
#pragma unroll
            for (int r = 0; r < 4; r++) dacc[mt][nb][r] = 0.f;
    float l0 = 0.f, l1 = 0.f;

    prefetch(0);

    for (int t = 0; t < 64; t++) {
        __syncthreads();                    // prior reads of buf (t+1)&1 done
        if (t < 63) { prefetch(t + 1); CP_WAIT1(); } else { CP_WAIT0(); }
        __syncthreads();                    // buf t visible
        const int buf = t & 1;

        // ---- QK: S[16i x 32j], single fp16 pass, ldmatrix B (swizzled) ----
        float s[4][4];
#pragma unroll
        for (int jq = 0; jq < 4; jq++)
#pragma unroll
            for (int r = 0; r < 4; r++) s[jq][r] = 0.f;
        const uint32_t qbase = smb + QJ_OFF + buf * QJ_BUF;
#pragma unroll
        for (int ks = 0; ks < 8; ks++) {
            uint32_t ch = (uint32_t)(((ks * 2 + qk_c0) ^ lr) << 4);
#pragma unroll
            for (int u = 0; u < 2; u++) {
                uint32_t r0, r1, r2, r3;
                LDSM_X4(r0, r1, r2, r3, qbase + qjrow[u] + ch);
                uint32_t b0[2] = {r0, r1}, b1[2] = {r2, r3};
                mma_f16(s[u * 2],     ah[ks], b0);
                mma_f16(s[u * 2 + 1], ah[ks], b1);
            }
        }

        // ---- softmax (no-max; bounded scores) -> scaled fp16 P (swizzled) ----
        const float* mjb = (const float*)(sm + MJ_OFF + buf * 256);
        char* P = sm + P_OFF;
#pragma unroll
        for (int jq = 0; jq < 4; jq++) {
            int j8 = jh * 32 + jq * 8;
            float m0 = (mjb[j8 + 2 * tig]     - 1.f) * 1e8f;
            float m1 = (mjb[j8 + 2 * tig + 1] - 1.f) * 1e8f;
            float p0 = __expf(fmaf(s[jq][0], INVS, m0));
            float p1 = __expf(fmaf(s[jq][1], INVS, m1));
            float p2 = __expf(fmaf(s[jq][2], INVS, m0));
            float p3 = __expf(fmaf(s[jq][3], INVS, m1));
            l0 += p0 + p1; l1 += p2 + p3;
            __half2 q01 = __floats2half2_rn(p0 * PSC, p1 * PSC);
            __half2 q23 = __floats2half2_rn(p2 * PSC, p3 * PSC);
            int chn = ((jh * 4 + jq) ^ gid) << 4;   // row&7 == gid for both rows
            *(uint32_t*)(P + (g * 16 + gid)     * 128 + chn + tig * 4) = *(uint32_t*)&q01;
            *(uint32_t*)(P + (g * 16 + 8 + gid) * 128 + chn + tig * 4) = *(uint32_t*)&q23;
        }
        asm volatile("bar.sync %0, 64;" :: "r"(1 + g) : "memory");

        // ---- PV: dacc += feat @ P^T (ldmatrix A/B, swizzled) ----
        const uint32_t fbb = smb + FEAT_OFF + buf * FEAT_BUF;
#pragma unroll
        for (int ks = 0; ks < 4; ks++) {
            uint32_t bp0, bp1, bp2, bp3;
            LDSM_X4(bp0, bp1, bp2, bp3, pvbrow + (((ks * 2 + pvb_c0) ^ lr) << 4));
            uint32_t bL[2] = {bp0, bp1}, bR[2] = {bp2, bp3};
            uint32_t fch = (uint32_t)(((ks * 2 + pva_c0) ^ lr) << 4);
#pragma unroll
            for (int mt = 0; mt < 8; mt++) {
                uint32_t a0, a1, a2, a3;
                LDSM_X4(a0, a1, a2, a3, fbb + pvarow + mt * (16 * 128) + fch);
                uint32_t aa[4] = {a0, a1, a2, a3};
                mma_f16(dacc[mt][0], aa, bL);
                mma_f16(dacc[mt][1], aa, bR);
            }
        }
    }

    // ---- l reduction (quad shuffle + cross-warp-pair via SMEM) ----
    l0 += __shfl_xor_sync(0xFFFFFFFFu, l0, 1);
    l0 += __shfl_xor_sync(0xFFFFFFFFu, l0, 2);
    l1 += __shfl_xor_sync(0xFFFFFFFFu, l1, 1);
    l1 += __shfl_xor_sync(0xFFFFFFFFu, l1, 2);
    float* lred = (float*)(sm + LRED_OFF);
    __syncthreads();
    if (jh == 0 && tig == 0) { lred[g * 16 + gid] = l0; lred[g * 16 + 8 + gid] = l1; }
    __syncthreads();
    if (jh == 1 && tig == 0) { lred[g * 16 + gid] += l0; lred[g * 16 + 8 + gid] += l1; }
    __syncthreads();

    // ---- epilogue: out[c][i] = dacc * 64 / l * mask_i ----
#pragma unroll
    for (int nb = 0; nb < 2; nb++) {
        int i0 = g * 16 + nb * 8 + 2 * tig;
        float r0 = mask[n * HW + ib + i0]     * PSCI / fmaxf(lred[i0],     1e-30f);
        float r1 = mask[n * HW + ib + i0 + 1] * PSCI / fmaxf(lred[i0 + 1], 1e-30f);
#pragma unroll
        for (int mt = 0; mt < 8; mt++) {
            int c = jh * 128 + mt * 16 + gid;
            float2 v0 = make_float2(dacc[mt][nb][0] * r0, dacc[mt][nb][1] * r1);
            float2 v1 = make_float2(dacc[mt][nb][2] * r0, dacc[mt][nb][3] * r1);
            *(float2*)(out + ((size_t)(n * CO + c))     * HW + ib + i0) = v0;
            *(float2*)(out + ((size_t)(n * CO + c + 8)) * HW + ib + i0) = v1;
        }
    }
}

extern "C" void kernel_launch(void* const* d_in, const int* in_sizes, int n_in,
                              void* d_out, int out_size) {
    const float* x    = (const float*)d_in[0];
    const float* mask = (const float*)d_in[1];
    prep_kernel<<<1, CO + CA>>>((const float*)d_in[3], (const float*)d_in[4],
                                (const float*)d_in[5], (const float*)d_in[6],
                                (const float*)d_in[8], (const float*)d_in[9],
                                (const float*)d_in[10], (const float*)d_in[11]);
    dim3 gproj(HW / 64, (CO + CA) / 64, NB);
    proj_kernel<<<gproj, 256>>>(x, (const float*)d_in[2], (const float*)d_in[7]);

    cudaFuncSetAttribute(flash_kernel, cudaFuncAttributeMaxDynamicSharedMemorySize, SMEM_TOTAL);
    dim3 gfl(HW / 64, NB);
    flash_kernel<<<gfl, 256, SMEM_TOTAL>>>(mask, (float*)d_out);
}

// round 9
// speedup vs baseline: 2.2496x; 1.4505x over previous
#include <cuda_runtime.h>
#include <cuda_bf16.h>
#include <cuda_fp16.h>
#include <cstdint>

#define NB 8
#define HW 4096
#define CI 256
#define CA 128
#define CO 256
#define INVS 0.08838834764831843f
#define PSC  0.015625f
#define PSCI 64.0f

// ---- flash SMEM layout ----
#define QJ_OFF   0
#define QJ_BUF   16384
#define FEAT_OFF 32768
#define FEAT_BUF 32768
#define P_OFF    98304
#define MJ_OFF   106496
#define LRED_OFF 107008
#define SMEM_TOTAL 107520

// ---- proj SMEM layout ----
#define PW_OFF   0          // 2 x 16384 (128 o-rows x 128B)
#define PX_OFF   32768      // 2 x 16384 (64 c-rows x 256B)
#define QT_OFF   65536      // 128 x 272B transpose stage
#define PROJ_SMEM 100352

__device__ __half g_q[NB * HW * CA];
__device__ __half g_featT[(size_t)NB * CO * HW];
__device__ __half g_xh[(size_t)NB * CI * HW];
__device__ __half g_wh[(CO + CA) * CI];
__device__ float g_scale[CO + CA];
__device__ float g_bias[CO + CA];

__device__ __forceinline__ uint32_t smem_u32(const void* p) {
    uint32_t a;
    asm("{ .reg .u64 t; cvta.to.shared.u64 t, %1; cvt.u32.u64 %0, t; }" : "=r"(a) : "l"(p));
    return a;
}
#define CP16(dst, src) asm volatile("cp.async.cg.shared.global [%0], [%1], 16;" :: "r"(dst), "l"(src))
#define CP_COMMIT()    asm volatile("cp.async.commit_group;" ::: "memory")
#define CP_WAIT1()     asm volatile("cp.async.wait_group 1;" ::: "memory")
#define CP_WAIT0()     asm volatile("cp.async.wait_group 0;" ::: "memory")

#define LDSM_X4(r0, r1, r2, r3, addr) \
    asm volatile("ldmatrix.sync.aligned.m8n8.x4.shared.b16 {%0,%1,%2,%3}, [%4];" \
        : "=r"(r0), "=r"(r1), "=r"(r2), "=r"(r3) : "r"(addr))
#define LDSM_X4T(r0, r1, r2, r3, addr) \
    asm volatile("ldmatrix.sync.aligned.m8n8.x4.trans.shared.b16 {%0,%1,%2,%3}, [%4];" \
        : "=r"(r0), "=r"(r1), "=r"(r2), "=r"(r3) : "r"(addr))

__device__ __forceinline__ void mma_f16(float* d, const uint32_t* a, const uint32_t* b) {
    asm volatile("mma.sync.aligned.m16n8k16.row.col.f32.f16.f16.f32 "
        "{%0,%1,%2,%3}, {%4,%5,%6,%7}, {%8,%9}, {%0,%1,%2,%3};"
        : "+f"(d[0]), "+f"(d[1]), "+f"(d[2]), "+f"(d[3])
        : "r"(a[0]), "r"(a[1]), "r"(a[2]), "r"(a[3]), "r"(b[0]), "r"(b[1]));
}

__global__ void prep_kernel(const float* __restrict__ rg, const float* __restrict__ rb,
                            const float* __restrict__ rm, const float* __restrict__ rv,
                            const float* __restrict__ ag, const float* __restrict__ ab,
                            const float* __restrict__ am, const float* __restrict__ av) {
    int o = threadIdx.x;
    if (o < CO) {
        float inv = rg[o] * rsqrtf(rv[o] + 1e-5f);
        g_scale[o] = inv; g_bias[o] = rb[o] - rm[o] * inv;
    } else if (o < CO + CA) {
        int a = o - CO;
        float inv = ag[a] * rsqrtf(av[a] + 1e-5f);
        g_scale[o] = inv; g_bias[o] = ab[a] - am[a] * inv;
    }
}

// fp32 -> fp16: x (2,097,152 float4) then W (24,576 float4)
#define XN4 2097152
#define WN4 24576
__global__ __launch_bounds__(256) void convert_kernel(const float4* __restrict__ x,
                                                      const float4* __restrict__ rw,
                                                      const float4* __restrict__ aw) {
    int idx = blockIdx.x * 256 + threadIdx.x;
    if (idx < XN4) {
        float4 v = x[idx];
        __half2 h0 = __floats2half2_rn(v.x, v.y);
        __half2 h1 = __floats2half2_rn(v.z, v.w);
        *(uint2*)(g_xh + (size_t)idx * 4) = make_uint2(*(uint32_t*)&h0, *(uint32_t*)&h1);
    } else {
        int widx = idx - XN4;
        if (widx < WN4) {
            float4 v = (widx < 16384) ? rw[widx] : aw[widx - 16384];
            __half2 h0 = __floats2half2_rn(v.x, v.y);
            __half2 h1 = __floats2half2_rn(v.z, v.w);
            *(uint2*)(g_wh + widx * 4) = make_uint2(*(uint32_t*)&h0, *(uint32_t*)&h1);
        }
    }
}

// HMMA projection: D[o,p] = W[o,c] @ x[c,p]; BN+ReLU epilogue -> fp16 featT / q
__global__ __launch_bounds__(256) void proj_mma(float* dummy) {
    extern __shared__ __align__(16) char sm[];
    const uint32_t smb = smem_u32(sm);
    const int pb = blockIdx.x * 128, ob = blockIdx.y, n = blockIdx.z;
    const int tid = threadIdx.x, w = tid >> 5, lane = tid & 31;
    const int gid = lane >> 2, tig = lane & 3;
    const int lq = lane >> 3, lr = lane & 7;
    const int wo = w & 3, wp = w >> 2;

    // hoisted ldmatrix addressing (swizzle XOR key is lr for all reads)
    uint32_t arow[2];
#pragma unroll
    for (int mt = 0; mt < 2; mt++)
        arow[mt] = (uint32_t)((wo * 32 + mt * 16 + ((lq & 1) ? 8 : 0) + lr) * 128);
    const int ac0 = (lq & 2) >> 1;
    const uint32_t brow0 = (uint32_t)((((lq & 1) ? 8 : 0) + lr) * 256);
    const int bc0 = wp * 8 + ((lq & 2) >> 1);

    auto loadchunk = [&](int c, int buf) {
        const uint32_t wsb = smb + PW_OFF + buf * 16384;
#pragma unroll
        for (int it = 0; it < 4; it++) {
            int e = tid + it * 256, row = e >> 3, ch = e & 7;
            CP16(wsb + row * 128 + ((ch ^ (row & 7)) << 4),
                 (const char*)(g_wh + (ob * 128 + row) * CI + c * 64 + ch * 8));
        }
        const uint32_t xsb = smb + PX_OFF + buf * 16384;
#pragma unroll
        for (int it = 0; it < 4; it++) {
            int e = tid + it * 256, row = e >> 4, ch = e & 15;
            CP16(xsb + row * 256 + ((ch ^ (row & 7)) << 4),
                 (const char*)(g_xh + ((size_t)(n * CI + c * 64 + row)) * HW + pb + ch * 8));
        }
        CP_COMMIT();
    };

    float acc[2][8][4];
#pragma unroll
    for (int mt = 0; mt < 2; mt++)
#pragma unroll
        for (int nb = 0; nb < 8; nb++)
#pragma unroll
            for (int r = 0; r < 4; r++) acc[mt][nb][r] = 0.f;

    loadchunk(0, 0);
    for (int c = 0; c < 4; c++) {
        __syncthreads();
        if (c < 3) { loadchunk(c + 1, (c + 1) & 1); CP_WAIT1(); } else { CP_WAIT0(); }
        __syncthreads();
        const int buf = c & 1;
        const uint32_t wsb = smb + PW_OFF + buf * 16384;
        const uint32_t xsb = smb + PX_OFF + buf * 16384;
#pragma unroll
        for (int ks = 0; ks < 4; ks++) {
            uint32_t a[2][4];
#pragma unroll
            for (int mt = 0; mt < 2; mt++)
                LDSM_X4(a[mt][0], a[mt][1], a[mt][2], a[mt][3],
                        wsb + arow[mt] + (((ks * 2 + ac0) ^ lr) << 4));
            const uint32_t brb = xsb + brow0 + ks * 16 * 256;
#pragma unroll
            for (int u = 0; u < 4; u++) {
                uint32_t r0, r1, r2, r3;
                LDSM_X4T(r0, r1, r2, r3, brb + (((bc0 + u * 2) ^ lr) << 4));
                uint32_t bL[2] = {r0, r1}, bR[2] = {r2, r3};
                mma_f16(acc[0][u * 2],     a[0], bL);
                mma_f16(acc[0][u * 2 + 1], a[0], bR);
                mma_f16(acc[1][u * 2],     a[1], bL);
                mma_f16(acc[1][u * 2 + 1], a[1], bR);
            }
        }
    }
    __syncthreads();

    if (ob < 2) {
        // feat: write fp16 [n][o][p], p-contiguous half2
#pragma unroll
        for (int mt = 0; mt < 2; mt++) {
            int o = ob * 128 + wo * 32 + mt * 16 + gid;
            float sc0 = g_scale[o], bs0 = g_bias[o];
            float sc8 = g_scale[o + 8], bs8 = g_bias[o + 8];
#pragma unroll
            for (int nb = 0; nb < 8; nb++) {
                int p = pb + wp * 64 + nb * 8 + 2 * tig;
                float v0 = fmaxf(fmaf(acc[mt][nb][0], sc0, bs0), 0.f);
                float v1 = fmaxf(fmaf(acc[mt][nb][1], sc0, bs0), 0.f);
                float v2 = fmaxf(fmaf(acc[mt][nb][2], sc8, bs8), 0.f);
                float v3 = fmaxf(fmaf(acc[mt][nb][3], sc8, bs8), 0.f);
                __half2 h0 = __floats2half2_rn(v0, v1);
                __half2 h1 = __floats2half2_rn(v2, v3);
                *(uint32_t*)(g_featT + ((size_t)n * CO + o) * HW + p) = *(uint32_t*)&h0;
                *(uint32_t*)(g_featT + ((size_t)n * CO + o + 8) * HW + p) = *(uint32_t*)&h1;
            }
        }
    } else {
        // q: transpose through SMEM -> [n][p][k] coalesced
        __half* qsm = (__half*)(sm + QT_OFF);
#pragma unroll
        for (int mt = 0; mt < 2; mt++) {
            int ol = wo * 32 + mt * 16 + gid;
            float sc0 = g_scale[CO + ol], bs0 = g_bias[CO + ol];
            float sc8 = g_scale[CO + ol + 8], bs8 = g_bias[CO + ol + 8];
#pragma unroll
            for (int nb = 0; nb < 8; nb++) {
                int pl = wp * 64 + nb * 8 + 2 * tig;
                qsm[pl * 136 + ol]           = __float2half(fmaxf(fmaf(acc[mt][nb][0], sc0, bs0), 0.f));
                qsm[(pl + 1) * 136 + ol]     = __float2half(fmaxf(fmaf(acc[mt][nb][1], sc0, bs0), 0.f));
                qsm[pl * 136 + ol + 8]       = __float2half(fmaxf(fmaf(acc[mt][nb][2], sc8, bs8), 0.f));
                qsm[(pl + 1) * 136 + ol + 8] = __float2half(fmaxf(fmaf(acc[mt][nb][3], sc8, bs8), 0.f));
            }
        }
        __syncthreads();
#pragma unroll
        for (int it = 0; it < 8; it++) {
            int e = tid + it * 256, row = e >> 4, ch = e & 15;
            *(uint4*)(g_q + ((size_t)(n * HW + pb + row)) * CA + ch * 8) =
                *(uint4*)((char*)qsm + row * 272 + ch * 16);
        }
    }
}

// flash attention: fp16 HMMA, XOR-swizzled SMEM, 2 CTAs/SM (unchanged from R8)
__global__ __launch_bounds__(256, 2) void flash_kernel(const float* __restrict__ mask,
                                                       float* __restrict__ out) {
    extern __shared__ __align__(16) char sm[];
    const uint32_t smb = smem_u32(sm);
    const int n = blockIdx.y, ib = blockIdx.x * 64;
    const int tid = threadIdx.x, w = tid >> 5, lane = tid & 31;
    const int gid = lane >> 2, tig = lane & 3;
    const int g = w >> 1, jh = w & 1;
    const int lq = lane >> 3, lr = lane & 7;

    uint32_t qjrow[2];
#pragma unroll
    for (int u = 0; u < 2; u++)
        qjrow[u] = (uint32_t)((jh * 32 + u * 16 + ((lq & 2) ? 8 : 0) + lr) * 256);
    const int qk_c0 = lq & 1;
    const uint32_t pvarow = (uint32_t)((jh * 128 + ((lq & 1) ? 8 : 0) + lr) * 128);
    const int pva_c0 = (lq & 2) >> 1;
    const uint32_t pvbrow = smb + P_OFF + (uint32_t)((g * 16 + ((lq & 2) ? 8 : 0) + lr) * 128);
    const int pvb_c0 = lq & 1;

    uint32_t ah[8][4];
    {
        const size_t r0 = (size_t)(n * HW + ib + g * 16 + gid) * CA;
        const size_t r1 = r0 + 8 * CA;
#pragma unroll
        for (int ks = 0; ks < 8; ks++) {
            int c0 = ks * 16 + 2 * tig;
            ah[ks][0] = *(const uint32_t*)(g_q + r0 + c0);
            ah[ks][1] = *(const uint32_t*)(g_q + r1 + c0);
            ah[ks][2] = *(const uint32_t*)(g_q + r0 + c0 + 8);
            ah[ks][3] = *(const uint32_t*)(g_q + r1 + c0 + 8);
        }
    }

    auto prefetch = [&](int t) {
        const int buf = t & 1, jb = t * 64;
        const uint32_t qh = smb + QJ_OFF + buf * QJ_BUF;
#pragma unroll
        for (int it = 0; it < 4; it++) {
            int e = tid + it * 256, row = e >> 4, ch = e & 15;
            CP16(qh + row * 256 + ((ch ^ (row & 7)) << 4),
                 (const char*)(g_q + (size_t)(n * HW + jb + row) * CA + ch * 8));
        }
        const uint32_t fb = smb + FEAT_OFF + buf * FEAT_BUF;
#pragma unroll
        for (int it = 0; it < 8; it++) {
            int e = tid + it * 256, row = e >> 3, ch = e & 7;
            CP16(fb + row * 128 + ((ch ^ (row & 7)) << 4),
                 (const char*)(g_featT + ((size_t)n * CO + row) * HW + jb + ch * 8));
        }
        if (tid < 16)
            CP16(smb + MJ_OFF + buf * 256 + tid * 16, (const char*)(mask + n * HW + jb + tid * 4));
        CP_COMMIT();
    };

    float dacc[8][2][4];
#pragma unroll
    for (int mt = 0; mt < 8; mt++)
#pragma unroll
        for (int nb = 0; nb < 2; nb++)
#pragma unroll
            for (int r = 0; r < 4; r++) dacc[mt][nb][r] = 0.f;
    float l0 = 0.f, l1 = 0.f;

    prefetch(0);

    for (int t = 0; t < 64; t++) {
        __syncthreads();
        if (t < 63) { prefetch(t + 1); CP_WAIT1(); } else { CP_WAIT0(); }
        __syncthreads();
        const int buf = t & 1;

        float s[4][4];
#pragma unroll
        for (int jq = 0; jq < 4; jq++)
#pragma unroll
            for (int r = 0; r < 4; r++) s[jq][r] = 0.f;
        const uint32_t qbase = smb + QJ_OFF + buf * QJ_BUF;
#pragma unroll
        for (int ks = 0; ks < 8; ks++) {
            uint32_t ch = (uint32_t)(((ks * 2 + qk_c0) ^ lr) << 4);
#pragma unroll
            for (int u = 0; u < 2; u++) {
                uint32_t r0, r1, r2, r3;
                LDSM_X4(r0, r1, r2, r3, qbase + qjrow[u] + ch);
                uint32_t b0[2] = {r0, r1}, b1[2] = {r2, r3};
                mma_f16(s[u * 2],     ah[ks], b0);
                mma_f16(s[u * 2 + 1], ah[ks], b1);
            }
        }

        const float* mjb = (const float*)(sm + MJ_OFF + buf * 256);
        char* P = sm + P_OFF;
#pragma unroll
        for (int jq = 0; jq < 4; jq++) {
            int j8 = jh * 32 + jq * 8;
            float m0 = (mjb[j8 + 2 * tig]     - 1.f) * 1e8f;
            float m1 = (mjb[j8 + 2 * tig + 1] - 1.f) * 1e8f;
            float p0 = __expf(fmaf(s[jq][0], INVS, m0));
            float p1 = __expf(fmaf(s[jq][1], INVS, m1));
            float p2 = __expf(fmaf(s[jq][2], INVS, m0));
            float p3 = __expf(fmaf(s[jq][3], INVS, m1));
            l0 += p0 + p1; l1 += p2 + p3;
            __half2 q01 = __floats2half2_rn(p0 * PSC, p1 * PSC);
            __half2 q23 = __floats2half2_rn(p2 * PSC, p3 * PSC);
            int chn = ((jh * 4 + jq) ^ gid) << 4;
            *(uint32_t*)(P + (g * 16 + gid)     * 128 + chn + tig * 4) = *(uint32_t*)&q01;
            *(uint32_t*)(P + (g * 16 + 8 + gid) * 128 + chn + tig * 4) = *(uint32_t*)&q23;
        }
        asm volatile("bar.sync %0, 64;" :: "r"(1 + g) : "memory");

        const uint32_t fbb = smb + FEAT_OFF + buf * FEAT_BUF;
#pragma unroll
        for (int ks = 0; ks < 4; ks++) {
            uint32_t bp0, bp1, bp2, bp3;
            LDSM_X4(bp0, bp1, bp2, bp3, pvbrow + (((ks * 2 + pvb_c0) ^ lr) << 4));
            uint32_t bL[2] = {bp0, bp1}, bR[2] = {bp2, bp3};
            uint32_t fch = (uint32_t)(((ks * 2 + pva_c0) ^ lr) << 4);
#pragma unroll
            for (int mt = 0; mt < 8; mt++) {
                uint32_t a0, a1, a2, a3;
                LDSM_X4(a0, a1, a2, a3, fbb + pvarow + mt * (16 * 128) + fch);
                uint32_t aa[4] = {a0, a1, a2, a3};
                mma_f16(dacc[mt][0], aa, bL);
                mma_f16(dacc[mt][1], aa, bR);
            }
        }
    }

    l0 += __shfl_xor_sync(0xFFFFFFFFu, l0, 1);
    l0 += __shfl_xor_sync(0xFFFFFFFFu, l0, 2);
    l1 += __shfl_xor_sync(0xFFFFFFFFu, l1, 1);
    l1 += __shfl_xor_sync(0xFFFFFFFFu, l1, 2);
    float* lred = (float*)(sm + LRED_OFF);
    __syncthreads();
    if (jh == 0 && tig == 0) { lred[g * 16 + gid] = l0; lred[g * 16 + 8 + gid] = l1; }
    __syncthreads();
    if (jh == 1 && tig == 0) { lred[g * 16 + gid] += l0; lred[g * 16 + 8 + gid] += l1; }
    __syncthreads();

#pragma unroll
    for (int nb = 0; nb < 2; nb++) {
        int i0 = g * 16 + nb * 8 + 2 * tig;
        float r0 = mask[n * HW + ib + i0]     * PSCI / fmaxf(lred[i0],     1e-30f);
        float r1 = mask[n * HW + ib + i0 + 1] * PSCI / fmaxf(lred[i0 + 1], 1e-30f);
#pragma unroll
        for (int mt = 0; mt < 8; mt++) {
            int c = jh * 128 + mt * 16 + gid;
            float2 v0 = make_float2(dacc[mt][nb][0] * r0, dacc[mt][nb][1] * r1);
            float2 v1 = make_float2(dacc[mt][nb][2] * r0, dacc[mt][nb][3] * r1);
            *(float2*)(out + ((size_t)(n * CO + c))     * HW + ib + i0) = v0;
            *(float2*)(out + ((size_t)(n * CO + c + 8)) * HW + ib + i0) = v1;
        }
    }
}

extern "C" void kernel_launch(void* const* d_in, const int* in_sizes, int n_in,
                              void* d_out, int out_size) {
    const float* x    = (const float*)d_in[0];
    const float* mask = (const float*)d_in[1];
    prep_kernel<<<1, CO + CA>>>((const float*)d_in[3], (const float*)d_in[4],
                                (const float*)d_in[5], (const float*)d_in[6],
                                (const float*)d_in[8], (const float*)d_in[9],
                                (const float*)d_in[10], (const float*)d_in[11]);
    convert_kernel<<<(XN4 + WN4) / 256, 256>>>((const float4*)x,
                                               (const float4*)d_in[2],
                                               (const float4*)d_in[7]);
    cudaFuncSetAttribute(proj_mma, cudaFuncAttributeMaxDynamicSharedMemorySize, PROJ_SMEM);
    dim3 gproj(HW / 128, 3, NB);
    proj_mma<<<gproj, 256, PROJ_SMEM>>>(nullptr);

    cudaFuncSetAttribute(flash_kernel, cudaFuncAttributeMaxDynamicSharedMemorySize, SMEM_TOTAL);
    dim3 gfl(HW / 64, NB);
    flash_kernel<<<gfl, 256, SMEM_TOTAL>>>(mask, (float*)d_out);
}